// round 9
// baseline (speedup 1.0000x reference)
#include <cuda_runtime.h>
#include <math.h>

#define NGRAPH 1024
#define TOPK 32
#define BS 256
#define NBLK 2048
#define CAP2 512                             // per-graph global candidate cap
#define CAP 2048                             // fallback smem cap
#define NEG_MIN (-3.4028234663852886e38f)    // np.finfo(float32).min == -FLT_MAX
#define THR 2.0f                             // prior threshold ~2 sigma

__device__ unsigned g_cand_fl[NGRAPH * CAP2];
__device__ int      g_cand_ix[NGRAPH * CAP2];
__device__ int      g_cand_cnt[NGRAPH];      // zero-init; rank_kernel re-zeros

// Order-preserving float->uint flip: larger float -> larger unsigned.
__device__ __forceinline__ unsigned flipf(float s) {
    unsigned u = __float_as_uint(s);
    return (u & 0x80000000u) ? ~u : (u | 0x80000000u);
}

// ---------------------------------------------------------------------------
// K1: role-split streaming kernel. Fill blocks do a PURE constant-store
// stream over out[]; scan blocks do a PURE load+test stream over scores[]
// (mask loaded only when a score exceeds THR, ~9% of vectors; edge_batch
// loaded only for actual candidates, ~1%). The two streams run concurrently
// on different SMs, so neither loop mixes loads and stores.
// ---------------------------------------------------------------------------
__global__ void __launch_bounds__(BS) scan_kernel(
    const float* __restrict__ scores,
    const int*   __restrict__ cmask,        // bool delivered as int32
    const int*   __restrict__ b32,          // edge_batch (int32 or int64 words)
    float* __restrict__ out,
    int E)
{
    const int nv = E >> 2;
    const int FILLB = (NBLK * 46) / 100;    // write share ~46% of traffic

    if (blockIdx.x < FILLB) {
        // ---- Pure fill stream ----
        const float4 v4 = make_float4(NEG_MIN, NEG_MIN, NEG_MIN, NEG_MIN);
        float4* o4 = (float4*)out;
        const int gid = blockIdx.x * BS + threadIdx.x;
        const int gsz = FILLB * BS;
        #pragma unroll 8
        for (int v = gid; v < nv; v += gsz) __stcs(o4 + v, v4);
        if (blockIdx.x == 0) {               // scalar tail (E % 4)
            for (int i = (nv << 2) + threadIdx.x; i < E; i += BS) out[i] = NEG_MIN;
        }
    } else {
        // ---- Pure scan stream ----
        const bool is64 = (b32[(E - 2) | 1] == 0);   // dtype sniff
        const float4* sc4 = (const float4*)scores;
        const int4*   cm4 = (const int4*)cmask;
        const int sb  = blockIdx.x - FILLB;
        const int nsb = NBLK - FILLB;
        const int gid = sb * BS + threadIdx.x;
        const int gsz = nsb * BS;
        #pragma unroll 8
        for (int v = gid; v < nv; v += gsz) {
            const float4 sc = __ldcs(sc4 + v);
            const bool t0 = sc.x > THR;
            const bool t1 = sc.y > THR;
            const bool t2 = sc.z > THR;
            const bool t3 = sc.w > THR;
            if (t0 | t1 | t2 | t3) {
                const int4 cm = __ldcs(cm4 + v);    // rare: mask load
                const int  i  = v << 2;
                #pragma unroll
                for (int w = 0; w < 4; ++w) {
                    const bool  t = (w == 0) ? t0 : (w == 1) ? t1 : (w == 2) ? t2 : t3;
                    const int   c = (w == 0) ? cm.x : (w == 1) ? cm.y : (w == 2) ? cm.z : cm.w;
                    const float s = (w == 0) ? sc.x : (w == 1) ? sc.y : (w == 2) ? sc.z : sc.w;
                    if (t && c) {
                        const int idx = i + w;
                        const int gph = is64 ? (int)((const long long*)b32)[idx] : b32[idx];
                        const int p   = atomicAdd(&g_cand_cnt[gph], 1);
                        if (p < CAP2) {
                            g_cand_fl[gph * CAP2 + p] = flipf(s);
                            g_cand_ix[gph * CAP2 + p] = idx;
                        }
                    }
                }
            }
        }
        if (sb == 0) {                       // scalar tail (E % 4)
            for (int i = (nv << 2) + threadIdx.x; i < E; i += BS) {
                const float s = scores[i];
                if (s > THR && cmask[i]) {
                    const int gph = is64 ? (int)((const long long*)b32)[i] : b32[i];
                    const int p   = atomicAdd(&g_cand_cnt[gph], 1);
                    if (p < CAP2) {
                        g_cand_fl[gph * CAP2 + p] = flipf(s);
                        g_cand_ix[gph * CAP2 + p] = i;
                    }
                }
            }
        }
    }
}

// ---------------------------------------------------------------------------
// K2: per-graph exact top-K from the candidate list via byte-radix select in
// smem (stable tie-break: score desc, index asc); segmented log-denominator;
// kept writes. Exact gmem radix fallback when the list is unusable.
// ---------------------------------------------------------------------------
__global__ void __launch_bounds__(BS) rank_kernel(
    const float* __restrict__ logits,
    const float* __restrict__ scores,
    const float* __restrict__ stop,
    const int*   __restrict__ cmask,
    const int*   __restrict__ b32,
    float* __restrict__ out,
    int E)
{
    __shared__ unsigned buf_fl[CAP];
    __shared__ int      buf_ix[CAP];
    __shared__ unsigned tb_fl[CAP2];
    __shared__ int      tb_ix[CAP2];
    __shared__ int      s_kidx[TOPK];
    __shared__ float    s_lv[TOPK];
    __shared__ float    s_ld;
    __shared__ int      seg[2];
    __shared__ int      hist[2048];
    __shared__ int      s_found, s_bin, s_above, s_minix, s_kcnt;
    __shared__ unsigned s_Tf;
    __shared__ int      s_Tix;

    const int g   = blockIdx.x;
    const int tid = threadIdx.x;
    const int cnt = g_cand_cnt[g];

    int kc;
    if (cnt >= TOPK && cnt <= CAP2) {
        // ---- Fast path: byte-radix select over the smem candidate list ----
        for (int j = tid; j < cnt; j += BS) {
            buf_fl[j] = g_cand_fl[g * CAP2 + j];
            buf_ix[j] = g_cand_ix[g * CAP2 + j];
        }
        __syncthreads();

        unsigned prefix = 0, pmask = 0;
        int above = 0;
        for (int lvl = 0; lvl < 4; ++lvl) {
            const int shift = 24 - 8 * lvl;
            if (tid < 256) hist[tid] = 0;
            __syncthreads();
            for (int j = tid; j < cnt; j += BS) {
                const unsigned fl = buf_fl[j];
                if ((fl & pmask) == prefix)
                    atomicAdd(&hist[(fl >> shift) & 0xFF], 1);
            }
            __syncthreads();

            if (tid < 32) {
                const int lane = tid;
                const int Kp   = TOPK - above;
                int cum = 0;
                for (int base = 255; base >= 0; base -= 32) {
                    int bin = base - lane;
                    int c   = hist[bin];
                    int incl = c;
                    #pragma unroll
                    for (int off = 1; off < 32; off <<= 1) {
                        int v = __shfl_up_sync(0xffffffffu, incl, off);
                        if (lane >= off) incl += v;
                    }
                    unsigned bal = __ballot_sync(0xffffffffu, cum + incl >= Kp);
                    if (bal) {
                        int first = __ffs(bal) - 1;
                        if (lane == first) { s_bin = bin; s_above = cum + incl - c; }
                        break;
                    }
                    cum += __shfl_sync(0xffffffffu, incl, 31);
                }
            }
            __syncthreads();

            const int b = s_bin;
            const int n = hist[b];
            above  += s_above;
            prefix |= ((unsigned)b) << shift;
            pmask  |= 0xFFu << shift;
            __syncthreads();                    // hist reads done

            if (n <= 64 || lvl == 3) {
                if (tid == 0) s_kcnt = 0;
                __syncthreads();
                for (int j = tid; j < cnt; j += BS) {
                    const unsigned fl = buf_fl[j];
                    if ((fl & pmask) == prefix) {
                        int p = atomicAdd(&s_kcnt, 1);
                        tb_fl[p] = fl; tb_ix[p] = buf_ix[j];
                    }
                }
                __syncthreads();
                const int nn = s_kcnt;
                const int r  = TOPK - 1 - above;
                for (int j = tid; j < nn; j += BS) {
                    const unsigned fj = tb_fl[j];
                    const int      ij = tb_ix[j];
                    int rk = 0;
                    for (int l = 0; l < nn; ++l) {
                        const unsigned fl2 = tb_fl[l];
                        rk += (fl2 > fj) || (fl2 == fj && tb_ix[l] < ij);
                    }
                    if (rk == r) { s_Tf = fj; s_Tix = ij; }
                }
                __syncthreads();
                break;
            }
        }

        const unsigned Tf = s_Tf; const int Tix = s_Tix;
        if (tid == 0) s_kcnt = 0;
        __syncthreads();
        for (int j = tid; j < cnt; j += BS) {
            const unsigned fl = buf_fl[j];
            if (fl > Tf || (fl == Tf && buf_ix[j] <= Tix)) {
                int p = atomicAdd(&s_kcnt, 1);
                s_kidx[p] = buf_ix[j];
            }
        }
        kc = TOPK;
        __syncthreads();
    } else {
        // ---- Fallback: segment bounds + exact 3-level radix over gmem ----
        if (tid < 2) {
            const int target = g + tid;
            int lo = 0;
            if (target == NGRAPH) lo = E;
            else if (target > 0) {
                const bool is64 = (b32[(E - 2) | 1] == 0);
                int hi = E;
                if (is64) {
                    const long long* b = (const long long*)b32;
                    const long long key = (long long)target;
                    while (lo < hi) { int mid = (lo + hi) >> 1; if (b[mid] < key) lo = mid + 1; else hi = mid; }
                } else {
                    while (lo < hi) { int mid = (lo + hi) >> 1; if (b32[mid] < target) lo = mid + 1; else hi = mid; }
                }
            }
            seg[tid] = lo;
        }
        __syncthreads();
        const int s0 = seg[0], s1 = seg[1];

        unsigned prefix = 0, pmask = 0;
        int  above = 0;
        bool keepall = false, have_thr = false;

        for (int lvl = 0; lvl < 3; ++lvl) {
            const int      shift = (lvl == 0) ? 21 : (lvl == 1) ? 10 : 0;
            const unsigned mw    = (lvl == 2) ? 0x3FFu : 0x7FFu;

            for (int j = tid; j < 2048; j += BS) hist[j] = 0;
            if (tid == 0) s_found = 0;
            __syncthreads();

            for (int i = s0 + tid; i < s1; i += BS) {
                if (cmask[i] != 0) {
                    unsigned fl = flipf(scores[i]);
                    if ((fl & pmask) == prefix)
                        atomicAdd(&hist[(fl >> shift) & mw], 1);
                }
            }
            __syncthreads();

            if (tid < 32) {
                const int lane = tid;
                const int Kp   = TOPK - above;
                int cum = 0;
                for (int base = (int)mw; base >= 0; base -= 32) {
                    int bin = base - lane;
                    int c   = (bin >= 0) ? hist[bin] : 0;
                    int incl = c;
                    #pragma unroll
                    for (int off = 1; off < 32; off <<= 1) {
                        int v = __shfl_up_sync(0xffffffffu, incl, off);
                        if (lane >= off) incl += v;
                    }
                    unsigned bal = __ballot_sync(0xffffffffu, cum + incl >= Kp);
                    if (bal) {
                        int first = __ffs(bal) - 1;
                        if (lane == first) { s_bin = bin; s_above = cum + incl - c; s_found = 1; }
                        break;
                    }
                    cum += __shfl_sync(0xffffffffu, incl, 31);
                }
            }
            __syncthreads();

            if (!s_found) { keepall = true; break; }

            const int b = s_bin;
            above  += s_above;
            const int n = hist[b];
            prefix |= ((unsigned)b) << shift;
            pmask  |= mw << shift;
            __syncthreads();

            if (n <= CAP) {
                if (tid == 0) s_kcnt = 0;
                __syncthreads();
                for (int i = s0 + tid; i < s1; i += BS) {
                    if (cmask[i] != 0) {
                        unsigned fl = flipf(scores[i]);
                        if ((fl & pmask) == prefix) {
                            int p = atomicAdd(&s_kcnt, 1);
                            buf_fl[p] = fl; buf_ix[p] = i;
                        }
                    }
                }
                __syncthreads();
                const int nn = s_kcnt;
                const int r  = TOPK - 1 - above;
                for (int j = tid; j < nn; j += BS) {
                    unsigned fj = buf_fl[j]; int ij = buf_ix[j];
                    int rk = 0;
                    for (int l = 0; l < nn; ++l) {
                        unsigned fl2 = buf_fl[l];
                        rk += (fl2 > fj) || (fl2 == fj && buf_ix[l] < ij);
                    }
                    if (rk == r) { s_Tf = fj; s_Tix = ij; }
                }
                have_thr = true;
                __syncthreads();
                break;
            }
        }

        unsigned Tf; int Tix;
        if (keepall)       { Tf = 0u;   Tix = 0x7FFFFFFF; }
        else if (have_thr) { Tf = s_Tf; Tix = s_Tix; }
        else {
            const int m = TOPK - above;
            int last = -1;
            for (int t = 0; t < m; ++t) {
                if (tid == 0) s_minix = 0x7FFFFFFF;
                __syncthreads();
                for (int i = s0 + tid; i < s1; i += BS) {
                    if (cmask[i] != 0 && i > last) {
                        if (flipf(scores[i]) == prefix) atomicMin(&s_minix, i);
                    }
                }
                __syncthreads();
                last = s_minix;
                __syncthreads();
            }
            Tf = prefix; Tix = last;
        }

        if (tid == 0) s_kcnt = 0;
        __syncthreads();
        for (int i = s0 + tid; i < s1; i += BS) {
            if (cmask[i] != 0) {
                unsigned fl = flipf(scores[i]);
                if (fl > Tf || (fl == Tf && i <= Tix)) {
                    int p = atomicAdd(&s_kcnt, 1);
                    if (p < TOPK) s_kidx[p] = i;
                }
            }
        }
        __syncthreads();
        kc = min(s_kcnt, TOPK);
    }

    // ---- Segmented log-denominator over the <=32 kept logits + stop ----
    if (tid < kc) s_lv[tid] = logits[s_kidx[tid]];   // TEMP == 1.0
    __syncthreads();

    if (tid < 32) {
        float v = (tid < kc) ? s_lv[tid] : -INFINITY;
        float mx = v;
        #pragma unroll
        for (int off = 16; off; off >>= 1) mx = fmaxf(mx, __shfl_xor_sync(0xffffffffu, mx, off));
        float e = (tid < kc) ? expf(v - mx) : 0.0f;
        #pragma unroll
        for (int off = 16; off; off >>= 1) e += __shfl_xor_sync(0xffffffffu, e, off);
        if (tid == 0) {
            float st = stop[g];
            float ld;
            if (kc == 0) ld = st;
            else {
                float lse = logf(e) + mx;
                float a = fmaxf(lse, st), b2 = fminf(lse, st);
                ld = a + log1pf(expf(b2 - a));
            }
            s_ld = ld;
        }
    }
    __syncthreads();

    if (tid < kc) out[s_kidx[tid]] = s_lv[tid] - s_ld;

    // Reset this graph's counter for the next (graph-replayed) run.
    if (tid == 0) g_cand_cnt[g] = 0;
}

extern "C" void kernel_launch(void* const* d_in, const int* in_sizes, int n_in,
                              void* d_out, int out_size) {
    const float* logits = (const float*)d_in[0];
    const float* scores = (const float*)d_in[1];
    const float* stop   = (const float*)d_in[2];
    const int*   batch  = (const int*)d_in[3];
    const int*   cmask  = (const int*)d_in[4];
    float* out = (float*)d_out;
    const int E = in_sizes[0];

    scan_kernel<<<NBLK, BS>>>(scores, cmask, batch, out, E);
    rank_kernel<<<NGRAPH, BS>>>(logits, scores, stop, cmask, batch, out, E);
}

// round 10
// speedup vs baseline: 1.1287x; 1.1287x over previous
#include <cuda_runtime.h>
#include <math.h>

#define NGRAPH 1024
#define TOPK 32
#define BS 256
#define NBLK 2048
#define QCAP 1024                            // per-block smem hit queue
#define CAP2 512                             // per-graph global candidate cap
#define CAP 2048                             // fallback smem cap
#define NEG_MIN (-3.4028234663852886e38f)    // np.finfo(float32).min == -FLT_MAX
#define THR 2.0f                             // prior threshold ~2 sigma

__device__ unsigned g_cand_fl[NGRAPH * CAP2];
__device__ int      g_cand_ix[NGRAPH * CAP2];
__device__ int      g_cand_cnt[NGRAPH];      // zero-init; rank_kernel re-zeros

// Order-preserving float->uint flip: larger float -> larger unsigned.
__device__ __forceinline__ unsigned flipf(float s) {
    unsigned u = __float_as_uint(s);
    return (u & 0x80000000u) ? ~u : (u | 0x80000000u);
}

__device__ __forceinline__ void push_direct(
    const int* __restrict__ cmask, const int* __restrict__ b32,
    bool is64, int idx, float s)
{
    if (cmask[idx]) {
        const int gph = is64 ? (int)((const long long*)b32)[idx] : b32[idx];
        const int p   = atomicAdd(&g_cand_cnt[gph], 1);
        if (p < CAP2) {
            g_cand_fl[gph * CAP2 + p] = flipf(s);
            g_cand_ix[gph * CAP2 + p] = idx;
        }
    }
}

// ---------------------------------------------------------------------------
// K1: streaming scan. Hot loop touches ONLY scores (read) and out (fill
// write); threshold hits go to a per-block smem queue (no gmem dependency on
// the critical path). A drain phase then loads cmask for all queued hits in
// parallel (independent loads -> high MLP), filters, and pushes survivors to
// the owning graph's global candidate list.
// ---------------------------------------------------------------------------
__global__ void __launch_bounds__(BS) scan_kernel(
    const float* __restrict__ scores,
    const int*   __restrict__ cmask,        // bool delivered as int32
    const int*   __restrict__ b32,          // edge_batch (int32 or int64 words)
    float* __restrict__ out,
    int E)
{
    __shared__ int   q_cnt;
    __shared__ float q_sc[QCAP];
    __shared__ int   q_ix[QCAP];

    const int  nv   = E >> 2;
    const int  gid  = blockIdx.x * BS + threadIdx.x;
    const int  gsz  = NBLK * BS;
    const bool is64 = (b32[(E - 2) | 1] == 0);   // dtype sniff (L1-broadcast)
    const float4 v4 = make_float4(NEG_MIN, NEG_MIN, NEG_MIN, NEG_MIN);

    const float4* sc4 = (const float4*)scores;
    float4*       o4  = (float4*)out;

    if (threadIdx.x == 0) q_cnt = 0;
    __syncthreads();

    // ---- Hot loop: pure stream + smem-queue push ----
    #pragma unroll 4
    for (int v = gid; v < nv; v += gsz) {
        const float4 sc = __ldcs(sc4 + v);
        __stcs(o4 + v, v4);
        const bool t0 = sc.x > THR;
        const bool t1 = sc.y > THR;
        const bool t2 = sc.z > THR;
        const bool t3 = sc.w > THR;
        if (t0 | t1 | t2 | t3) {
            const int i = v << 2;
            #pragma unroll
            for (int w = 0; w < 4; ++w) {
                const bool  t = (w == 0) ? t0 : (w == 1) ? t1 : (w == 2) ? t2 : t3;
                const float s = (w == 0) ? sc.x : (w == 1) ? sc.y : (w == 2) ? sc.z : sc.w;
                if (t) {
                    const int p = atomicAdd(&q_cnt, 1);
                    if (p < QCAP) { q_sc[p] = s; q_ix[p] = i + w; }
                    else          push_direct(cmask, b32, is64, i + w, s);  // overflow (never in practice)
                }
            }
        }
    }
    // scalar tail (E % 4)
    if (blockIdx.x == 0) {
        for (int i = (nv << 2) + threadIdx.x; i < E; i += BS) {
            const float s = scores[i];
            out[i] = NEG_MIN;
            if (s > THR) {
                const int p = atomicAdd(&q_cnt, 1);
                if (p < QCAP) { q_sc[p] = s; q_ix[p] = i; }
                else          push_direct(cmask, b32, is64, i, s);
            }
        }
    }
    __syncthreads();

    // ---- Drain: parallel mask filter + global push ----
    const int n = min(q_cnt, QCAP);
    for (int j = threadIdx.x; j < n; j += BS) {
        const int idx = q_ix[j];
        if (cmask[idx]) {
            const int gph = is64 ? (int)((const long long*)b32)[idx] : b32[idx];
            const int p   = atomicAdd(&g_cand_cnt[gph], 1);
            if (p < CAP2) {
                g_cand_fl[gph * CAP2 + p] = flipf(q_sc[j]);
                g_cand_ix[gph * CAP2 + p] = idx;
            }
        }
    }
}

// ---------------------------------------------------------------------------
// K2: per-graph exact top-K from the candidate list via byte-radix select in
// smem (stable tie-break: score desc, index asc); segmented log-denominator;
// kept writes. Exact gmem radix fallback when the list is unusable.
// ---------------------------------------------------------------------------
__global__ void __launch_bounds__(BS) rank_kernel(
    const float* __restrict__ logits,
    const float* __restrict__ scores,
    const float* __restrict__ stop,
    const int*   __restrict__ cmask,
    const int*   __restrict__ b32,
    float* __restrict__ out,
    int E)
{
    __shared__ unsigned buf_fl[CAP];
    __shared__ int      buf_ix[CAP];
    __shared__ unsigned tb_fl[CAP2];
    __shared__ int      tb_ix[CAP2];
    __shared__ int      s_kidx[TOPK];
    __shared__ float    s_lv[TOPK];
    __shared__ float    s_ld;
    __shared__ int      seg[2];
    __shared__ int      hist[2048];
    __shared__ int      s_found, s_bin, s_above, s_minix, s_kcnt;
    __shared__ unsigned s_Tf;
    __shared__ int      s_Tix;

    const int g   = blockIdx.x;
    const int tid = threadIdx.x;
    const int cnt = g_cand_cnt[g];

    int kc;
    if (cnt >= TOPK && cnt <= CAP2) {
        // ---- Fast path: byte-radix select over the smem candidate list ----
        for (int j = tid; j < cnt; j += BS) {
            buf_fl[j] = g_cand_fl[g * CAP2 + j];
            buf_ix[j] = g_cand_ix[g * CAP2 + j];
        }
        __syncthreads();

        unsigned prefix = 0, pmask = 0;
        int above = 0;
        for (int lvl = 0; lvl < 4; ++lvl) {
            const int shift = 24 - 8 * lvl;
            if (tid < 256) hist[tid] = 0;
            __syncthreads();
            for (int j = tid; j < cnt; j += BS) {
                const unsigned fl = buf_fl[j];
                if ((fl & pmask) == prefix)
                    atomicAdd(&hist[(fl >> shift) & 0xFF], 1);
            }
            __syncthreads();

            if (tid < 32) {
                const int lane = tid;
                const int Kp   = TOPK - above;
                int cum = 0;
                for (int base = 255; base >= 0; base -= 32) {
                    int bin = base - lane;
                    int c   = hist[bin];
                    int incl = c;
                    #pragma unroll
                    for (int off = 1; off < 32; off <<= 1) {
                        int v = __shfl_up_sync(0xffffffffu, incl, off);
                        if (lane >= off) incl += v;
                    }
                    unsigned bal = __ballot_sync(0xffffffffu, cum + incl >= Kp);
                    if (bal) {
                        int first = __ffs(bal) - 1;
                        if (lane == first) { s_bin = bin; s_above = cum + incl - c; }
                        break;
                    }
                    cum += __shfl_sync(0xffffffffu, incl, 31);
                }
            }
            __syncthreads();

            const int b = s_bin;
            const int n = hist[b];
            above  += s_above;
            prefix |= ((unsigned)b) << shift;
            pmask  |= 0xFFu << shift;
            __syncthreads();                    // hist reads done

            if (n <= 64 || lvl == 3) {
                if (tid == 0) s_kcnt = 0;
                __syncthreads();
                for (int j = tid; j < cnt; j += BS) {
                    const unsigned fl = buf_fl[j];
                    if ((fl & pmask) == prefix) {
                        int p = atomicAdd(&s_kcnt, 1);
                        tb_fl[p] = fl; tb_ix[p] = buf_ix[j];
                    }
                }
                __syncthreads();
                const int nn = s_kcnt;
                const int r  = TOPK - 1 - above;
                for (int j = tid; j < nn; j += BS) {
                    const unsigned fj = tb_fl[j];
                    const int      ij = tb_ix[j];
                    int rk = 0;
                    for (int l = 0; l < nn; ++l) {
                        const unsigned fl2 = tb_fl[l];
                        rk += (fl2 > fj) || (fl2 == fj && tb_ix[l] < ij);
                    }
                    if (rk == r) { s_Tf = fj; s_Tix = ij; }
                }
                __syncthreads();
                break;
            }
        }

        const unsigned Tf = s_Tf; const int Tix = s_Tix;
        if (tid == 0) s_kcnt = 0;
        __syncthreads();
        for (int j = tid; j < cnt; j += BS) {
            const unsigned fl = buf_fl[j];
            if (fl > Tf || (fl == Tf && buf_ix[j] <= Tix)) {
                int p = atomicAdd(&s_kcnt, 1);
                s_kidx[p] = buf_ix[j];
            }
        }
        kc = TOPK;
        __syncthreads();
    } else {
        // ---- Fallback: segment bounds + exact 3-level radix over gmem ----
        if (tid < 2) {
            const int target = g + tid;
            int lo = 0;
            if (target == NGRAPH) lo = E;
            else if (target > 0) {
                const bool is64 = (b32[(E - 2) | 1] == 0);
                int hi = E;
                if (is64) {
                    const long long* b = (const long long*)b32;
                    const long long key = (long long)target;
                    while (lo < hi) { int mid = (lo + hi) >> 1; if (b[mid] < key) lo = mid + 1; else hi = mid; }
                } else {
                    while (lo < hi) { int mid = (lo + hi) >> 1; if (b32[mid] < target) lo = mid + 1; else hi = mid; }
                }
            }
            seg[tid] = lo;
        }
        __syncthreads();
        const int s0 = seg[0], s1 = seg[1];

        unsigned prefix = 0, pmask = 0;
        int  above = 0;
        bool keepall = false, have_thr = false;

        for (int lvl = 0; lvl < 3; ++lvl) {
            const int      shift = (lvl == 0) ? 21 : (lvl == 1) ? 10 : 0;
            const unsigned mw    = (lvl == 2) ? 0x3FFu : 0x7FFu;

            for (int j = tid; j < 2048; j += BS) hist[j] = 0;
            if (tid == 0) s_found = 0;
            __syncthreads();

            for (int i = s0 + tid; i < s1; i += BS) {
                if (cmask[i] != 0) {
                    unsigned fl = flipf(scores[i]);
                    if ((fl & pmask) == prefix)
                        atomicAdd(&hist[(fl >> shift) & mw], 1);
                }
            }
            __syncthreads();

            if (tid < 32) {
                const int lane = tid;
                const int Kp   = TOPK - above;
                int cum = 0;
                for (int base = (int)mw; base >= 0; base -= 32) {
                    int bin = base - lane;
                    int c   = (bin >= 0) ? hist[bin] : 0;
                    int incl = c;
                    #pragma unroll
                    for (int off = 1; off < 32; off <<= 1) {
                        int v = __shfl_up_sync(0xffffffffu, incl, off);
                        if (lane >= off) incl += v;
                    }
                    unsigned bal = __ballot_sync(0xffffffffu, cum + incl >= Kp);
                    if (bal) {
                        int first = __ffs(bal) - 1;
                        if (lane == first) { s_bin = bin; s_above = cum + incl - c; s_found = 1; }
                        break;
                    }
                    cum += __shfl_sync(0xffffffffu, incl, 31);
                }
            }
            __syncthreads();

            if (!s_found) { keepall = true; break; }

            const int b = s_bin;
            above  += s_above;
            const int n = hist[b];
            prefix |= ((unsigned)b) << shift;
            pmask  |= mw << shift;
            __syncthreads();

            if (n <= CAP) {
                if (tid == 0) s_kcnt = 0;
                __syncthreads();
                for (int i = s0 + tid; i < s1; i += BS) {
                    if (cmask[i] != 0) {
                        unsigned fl = flipf(scores[i]);
                        if ((fl & pmask) == prefix) {
                            int p = atomicAdd(&s_kcnt, 1);
                            buf_fl[p] = fl; buf_ix[p] = i;
                        }
                    }
                }
                __syncthreads();
                const int nn = s_kcnt;
                const int r  = TOPK - 1 - above;
                for (int j = tid; j < nn; j += BS) {
                    unsigned fj = buf_fl[j]; int ij = buf_ix[j];
                    int rk = 0;
                    for (int l = 0; l < nn; ++l) {
                        unsigned fl2 = buf_fl[l];
                        rk += (fl2 > fj) || (fl2 == fj && buf_ix[l] < ij);
                    }
                    if (rk == r) { s_Tf = fj; s_Tix = ij; }
                }
                have_thr = true;
                __syncthreads();
                break;
            }
        }

        unsigned Tf; int Tix;
        if (keepall)       { Tf = 0u;   Tix = 0x7FFFFFFF; }
        else if (have_thr) { Tf = s_Tf; Tix = s_Tix; }
        else {
            const int m = TOPK - above;
            int last = -1;
            for (int t = 0; t < m; ++t) {
                if (tid == 0) s_minix = 0x7FFFFFFF;
                __syncthreads();
                for (int i = s0 + tid; i < s1; i += BS) {
                    if (cmask[i] != 0 && i > last) {
                        if (flipf(scores[i]) == prefix) atomicMin(&s_minix, i);
                    }
                }
                __syncthreads();
                last = s_minix;
                __syncthreads();
            }
            Tf = prefix; Tix = last;
        }

        if (tid == 0) s_kcnt = 0;
        __syncthreads();
        for (int i = s0 + tid; i < s1; i += BS) {
            if (cmask[i] != 0) {
                unsigned fl = flipf(scores[i]);
                if (fl > Tf || (fl == Tf && i <= Tix)) {
                    int p = atomicAdd(&s_kcnt, 1);
                    if (p < TOPK) s_kidx[p] = i;
                }
            }
        }
        __syncthreads();
        kc = min(s_kcnt, TOPK);
    }

    // ---- Segmented log-denominator over the <=32 kept logits + stop ----
    if (tid < kc) s_lv[tid] = logits[s_kidx[tid]];   // TEMP == 1.0
    __syncthreads();

    if (tid < 32) {
        float v = (tid < kc) ? s_lv[tid] : -INFINITY;
        float mx = v;
        #pragma unroll
        for (int off = 16; off; off >>= 1) mx = fmaxf(mx, __shfl_xor_sync(0xffffffffu, mx, off));
        float e = (tid < kc) ? expf(v - mx) : 0.0f;
        #pragma unroll
        for (int off = 16; off; off >>= 1) e += __shfl_xor_sync(0xffffffffu, e, off);
        if (tid == 0) {
            float st = stop[g];
            float ld;
            if (kc == 0) ld = st;
            else {
                float lse = logf(e) + mx;
                float a = fmaxf(lse, st), b2 = fminf(lse, st);
                ld = a + log1pf(expf(b2 - a));
            }
            s_ld = ld;
        }
    }
    __syncthreads();

    if (tid < kc) out[s_kidx[tid]] = s_lv[tid] - s_ld;

    // Reset this graph's counter for the next (graph-replayed) run.
    if (tid == 0) g_cand_cnt[g] = 0;
}

extern "C" void kernel_launch(void* const* d_in, const int* in_sizes, int n_in,
                              void* d_out, int out_size) {
    const float* logits = (const float*)d_in[0];
    const float* scores = (const float*)d_in[1];
    const float* stop   = (const float*)d_in[2];
    const int*   batch  = (const int*)d_in[3];
    const int*   cmask  = (const int*)d_in[4];
    float* out = (float*)d_out;
    const int E = in_sizes[0];

    scan_kernel<<<NBLK, BS>>>(scores, cmask, batch, out, E);
    rank_kernel<<<NGRAPH, BS>>>(logits, scores, stop, cmask, batch, out, E);
}